// round 12
// baseline (speedup 1.0000x reference)
#include <cuda_runtime.h>

#define H 16
#define T 2048
#define D 1024
#define DH 64
#define N3 3072
#define PI 128

// ---------------- scratch (no allocations allowed) ----------------
__device__ float g_q[H*T*DH];
__device__ float g_k[H*T*DH];
__device__ float g_v[H*T*DH];
__device__ float g_ao[H*T*DH];
__device__ int   g_cum[T];
__device__ float g_ns[32][H*DH*DH];   // newstate partials per chunk

// ---------------- tf32 helpers ----------------
__device__ __forceinline__ unsigned tf32_of(float v) {
    unsigned r;
    asm("cvt.rna.tf32.f32 %0, %1;" : "=r"(r) : "f"(v));
    return r;
}
__device__ __forceinline__ void mma_tf32(float* d, const unsigned* a, const unsigned* b) {
    asm("mma.sync.aligned.m16n8k8.row.col.f32.tf32.tf32.f32 "
        "{%0,%1,%2,%3},{%4,%5,%6,%7},{%8,%9},{%0,%1,%2,%3};"
        : "+f"(d[0]), "+f"(d[1]), "+f"(d[2]), "+f"(d[3])
        : "r"(a[0]), "r"(a[1]), "r"(a[2]), "r"(a[3]), "r"(b[0]), "r"(b[1]));
}

// ---------------- cumsum of done (dtype auto-detect) ----------------
__global__ void cumsum_kernel(const unsigned char* __restrict__ done) {
    __shared__ int tsum[256];
    __shared__ int s_big, s_off4;
    int tid = threadIdx.x;
    if (tid == 0) { s_big = 0; s_off4 = 0; }
    __syncthreads();
    int big = 0, off4 = 0;
    for (int i = tid; i < 2048; i += 256) {
        unsigned char bb = done[i];
        if (bb > 1) big = 1;
        if (bb != 0 && (i & 3) != 0) off4 = 1;
    }
    if (big)  atomicOr(&s_big, 1);
    if (off4) atomicOr(&s_off4, 1);
    __syncthreads();
    int mode = s_big ? 2 : (s_off4 ? 0 : 1);  // 0=bool, 1=int32, 2=float32

    int loc[8]; int s = 0;
#pragma unroll
    for (int i = 0; i < 8; i++) {
        int t = tid*8 + i;
        int v;
        if (mode == 0)      v = (done[t] != 0);
        else if (mode == 1) v = (((const int*)done)[t] != 0);
        else                v = (((const float*)done)[t] != 0.0f);
        loc[i] = v; s += v;
    }
    tsum[tid] = s; __syncthreads();
    for (int off = 1; off < 256; off <<= 1) {
        int v = (tid >= off) ? tsum[tid - off] : 0;
        __syncthreads();
        tsum[tid] += v;
        __syncthreads();
    }
    int run = (tid > 0) ? tsum[tid-1] : 0;
#pragma unroll
    for (int i = 0; i < 8; i++) { run += loc[i]; g_cum[tid*8 + i] = run; }
}

// ---------------- tf32 3x GEMM core (shared by qkv and out projection) ----------
// Block tile 128(M) x 64(N), K panel 16. 256 threads = 8 warps, warp tile 32x32.
// A split into hi/lo tf32 stored [m][k] stride 20; B stored [k][n] stride 72.
#define AST 20
#define BST 72

struct FragAcc { float a[2][4][4]; };  // [m-tile][n-tile][frag]

__device__ __forceinline__ void gemm_tf32_panel(
    const unsigned (*Ah)[AST], const unsigned (*Al)[AST],
    const unsigned (*Bh)[BST], const unsigned (*Bl)[BST],
    int wm, int wn, int g, int tig, FragAcc& F)
{
#pragma unroll
    for (int ks = 0; ks < 16; ks += 8) {
        unsigned ah[2][4], al[2][4], bh[4][2], bl[4][2];
#pragma unroll
        for (int mt = 0; mt < 2; mt++) {
            int rb = wm + mt*16;
            ah[mt][0] = Ah[rb + g    ][ks + tig];
            ah[mt][1] = Ah[rb + g + 8][ks + tig];
            ah[mt][2] = Ah[rb + g    ][ks + tig + 4];
            ah[mt][3] = Ah[rb + g + 8][ks + tig + 4];
            al[mt][0] = Al[rb + g    ][ks + tig];
            al[mt][1] = Al[rb + g + 8][ks + tig];
            al[mt][2] = Al[rb + g    ][ks + tig + 4];
            al[mt][3] = Al[rb + g + 8][ks + tig + 4];
        }
#pragma unroll
        for (int nt = 0; nt < 4; nt++) {
            int cb = wn + nt*8;
            bh[nt][0] = Bh[ks + tig    ][cb + g];
            bh[nt][1] = Bh[ks + tig + 4][cb + g];
            bl[nt][0] = Bl[ks + tig    ][cb + g];
            bl[nt][1] = Bl[ks + tig + 4][cb + g];
        }
#pragma unroll
        for (int mt = 0; mt < 2; mt++)
#pragma unroll
            for (int nt = 0; nt < 4; nt++) {
                mma_tf32(F.a[mt][nt], ah[mt], bh[nt]);
                mma_tf32(F.a[mt][nt], al[mt], bh[nt]);
                mma_tf32(F.a[mt][nt], ah[mt], bl[nt]);
            }
    }
}

// qkv: x(2048x1024) @ w_qkv(1024x3072) + b, scatter to g_q/g_k/g_v (H,T,DH)
__global__ void qkv_gemm_kernel(const float* __restrict__ x,
                                const float* __restrict__ w,
                                const float* __restrict__ b) {
    __shared__ unsigned Ah[128][AST], Al[128][AST];
    __shared__ unsigned Bh[16][BST],  Bl[16][BST];
    int bm = blockIdx.y, bn = blockIdx.x;
    int tid = threadIdx.x;
    int warp = tid >> 5, lane = tid & 31;
    int g = lane >> 2, tig = lane & 3;
    int wm = (warp >> 1) * 32, wn = (warp & 1) * 32;

    FragAcc F;
#pragma unroll
    for (int mt = 0; mt < 2; mt++)
#pragma unroll
        for (int nt = 0; nt < 4; nt++)
#pragma unroll
            for (int e = 0; e < 4; e++) F.a[mt][nt][e] = 0.0f;

    int arow = tid >> 1, ac4 = (tid & 1) * 8;     // A: 128 rows x 16 cols, 8 floats/thread
    int brow = tid >> 4, bc4 = (tid & 15) * 4;    // B: 16 rows x 64 cols, 4 floats/thread

    for (int kt = 0; kt < D/16; kt++) {
        const float* ap = x + (bm*128 + arow)*D + kt*16 + ac4;
        float4 v0 = *(const float4*)(ap);
        float4 v1 = *(const float4*)(ap + 4);
        float va[8] = {v0.x,v0.y,v0.z,v0.w,v1.x,v1.y,v1.z,v1.w};
#pragma unroll
        for (int i = 0; i < 8; i++) {
            unsigned hv = tf32_of(va[i]);
            Ah[arow][ac4+i] = hv;
            Al[arow][ac4+i] = tf32_of(va[i] - __uint_as_float(hv));
        }
        float4 bv = *(const float4*)(w + (kt*16 + brow)*N3 + bn*64 + bc4);
        float vb[4] = {bv.x, bv.y, bv.z, bv.w};
#pragma unroll
        for (int i = 0; i < 4; i++) {
            unsigned hv = tf32_of(vb[i]);
            Bh[brow][bc4+i] = hv;
            Bl[brow][bc4+i] = tf32_of(vb[i] - __uint_as_float(hv));
        }
        __syncthreads();
        gemm_tf32_panel(Ah, Al, Bh, Bl, wm, wn, g, tig, F);
        __syncthreads();
    }

    // epilogue: d-frag (mt,nt): rows m0, m0+8; cols n0, n0+1
#pragma unroll
    for (int mt = 0; mt < 2; mt++) {
        int m0 = bm*128 + wm + mt*16 + g;
#pragma unroll
        for (int nt = 0; nt < 4; nt++) {
            int n0 = bn*64 + wn + nt*8 + 2*tig;
#pragma unroll
            for (int e = 0; e < 4; e++) {
                int m = m0 + (e >> 1) * 8;
                int n = n0 + (e & 1);
                float val = F.a[mt][nt][e] + b[n];
                int qkv = n >> 10;
                int h   = (n >> 6) & 15;
                int dh  = n & 63;
                float* dst = (qkv == 0) ? g_q : ((qkv == 1) ? g_k : g_v);
                dst[(h*T + m)*DH + dh] = val;
            }
        }
    }
}

// out projection: ao(T x D, head-chunked layout) @ w_out(1024x1024) + b_out
__global__ void out_gemm_kernel(const float* __restrict__ w,
                                const float* __restrict__ b,
                                float* __restrict__ xout) {
    __shared__ unsigned Ah[128][AST], Al[128][AST];
    __shared__ unsigned Bh[16][BST],  Bl[16][BST];
    int bm = blockIdx.y, bn = blockIdx.x;
    int tid = threadIdx.x;
    int warp = tid >> 5, lane = tid & 31;
    int g = lane >> 2, tig = lane & 3;
    int wm = (warp >> 1) * 32, wn = (warp & 1) * 32;

    FragAcc F;
#pragma unroll
    for (int mt = 0; mt < 2; mt++)
#pragma unroll
        for (int nt = 0; nt < 4; nt++)
#pragma unroll
            for (int e = 0; e < 4; e++) F.a[mt][nt][e] = 0.0f;

    int arow = tid >> 1, ac4 = (tid & 1) * 8;
    int brow = tid >> 4, bc4 = (tid & 15) * 4;
    int m = bm*128 + arow;

    for (int kt = 0; kt < D/16; kt++) {
        int k  = kt*16 + ac4;
        int hh = k >> 6, dh = k & 63;      // 8 consecutive k stay within one head chunk
        const float* ap = g_ao + (hh*T + m)*DH + dh;
        float4 v0 = *(const float4*)(ap);
        float4 v1 = *(const float4*)(ap + 4);
        float va[8] = {v0.x,v0.y,v0.z,v0.w,v1.x,v1.y,v1.z,v1.w};
#pragma unroll
        for (int i = 0; i < 8; i++) {
            unsigned hv = tf32_of(va[i]);
            Ah[arow][ac4+i] = hv;
            Al[arow][ac4+i] = tf32_of(va[i] - __uint_as_float(hv));
        }
        float4 bv = *(const float4*)(w + (kt*16 + brow)*D + bn*64 + bc4);
        float vb[4] = {bv.x, bv.y, bv.z, bv.w};
#pragma unroll
        for (int i = 0; i < 4; i++) {
            unsigned hv = tf32_of(vb[i]);
            Bh[brow][bc4+i] = hv;
            Bl[brow][bc4+i] = tf32_of(vb[i] - __uint_as_float(hv));
        }
        __syncthreads();
        gemm_tf32_panel(Ah, Al, Bh, Bl, wm, wn, g, tig, F);
        __syncthreads();
    }

#pragma unroll
    for (int mt = 0; mt < 2; mt++) {
        int m0 = bm*128 + wm + mt*16 + g;
#pragma unroll
        for (int nt = 0; nt < 4; nt++) {
            int n0 = bn*64 + wn + nt*8 + 2*tig;
#pragma unroll
            for (int e = 0; e < 4; e++) {
                int mm = m0 + (e >> 1) * 8;
                int n  = n0 + (e & 1);
                xout[mm*D + n] = F.a[mt][nt][e] + b[n];
            }
        }
    }
}

// ---------------- attention (round-6 known-good) ----------------
__global__ void attn_kernel(const float* __restrict__ state) {
    extern __shared__ float sm[];
    float* qs = sm;                   // [64][PI]  q transposed: qs[d][i]
    float* ks = qs + 64*PI;           // [64][68]  k transposed: ks[d][j] (also state)
    float* vs = ks + 64*68;           // [64][64]  vs[j][d]
    float* Ss = vs + 64*64;           // [64][PI]  S transposed: Ss[j][i]
    int*   cq = (int*)(Ss + 64*PI);   // [128]
    int*   ck = cq + 128;             // [64]

    int h  = blockIdx.y;
    int tb = blockIdx.x;
    int t0 = tb * 128;
    int tid = threadIdx.x;
    int tx = tid & 15, ty = tid >> 4;

    const float* qg = g_q + (h*T + t0)*DH;
#pragma unroll
    for (int r = 0; r < 8; r++) {
        int idx = tid + r*256;
        int i = idx >> 4, c4 = (idx & 15) * 4;
        float4 a = *(const float4*)(qg + i*DH + c4);
        qs[(c4+0)*PI + i] = a.x;
        qs[(c4+1)*PI + i] = a.y;
        qs[(c4+2)*PI + i] = a.z;
        qs[(c4+3)*PI + i] = a.w;
    }
    if (tid < 128) cq[tid] = g_cum[t0 + tid];
    __syncthreads();

    float acc[8][4] = {};
    int cum_t0 = cq[0];

    int sb_max = 2*tb + 1;
    for (int sb = 0; sb <= sb_max; sb++) {
        int s0 = sb * 64;
        if (g_cum[s0 + 63] < cum_t0) continue;

        const float* kg = g_k + (h*T + s0)*DH;
        const float* vg = g_v + (h*T + s0)*DH;
#pragma unroll
        for (int r = 0; r < 4; r++) {
            int idx = tid + r*256;
            int j = idx >> 4, c4 = (idx & 15) * 4;
            float4 a = *(const float4*)(kg + j*DH + c4);
            ks[(c4+0)*68 + j] = a.x;
            ks[(c4+1)*68 + j] = a.y;
            ks[(c4+2)*68 + j] = a.z;
            ks[(c4+3)*68 + j] = a.w;
            *(float4*)&vs[j*64 + c4] = *(const float4*)(vg + j*DH + c4);
        }
        if (tid < 64) ck[tid] = g_cum[s0 + tid];
        __syncthreads();

        float sacc[8][4] = {};
#pragma unroll 8
        for (int d = 0; d < 64; d++) {
            float4 a0 = *(const float4*)&qs[d*PI + ty*8];
            float4 a1 = *(const float4*)&qs[d*PI + ty*8 + 4];
            float4 bv = *(const float4*)&ks[d*68 + tx*4];
            float aa[8] = {a0.x,a0.y,a0.z,a0.w,a1.x,a1.y,a1.z,a1.w};
            float bb[4] = {bv.x,bv.y,bv.z,bv.w};
#pragma unroll
            for (int i = 0; i < 8; i++)
#pragma unroll
                for (int j = 0; j < 4; j++) sacc[i][j] += aa[i] * bb[j];
        }
#pragma unroll
        for (int j = 0; j < 4; j++) {
            int s  = s0 + tx*4 + j;
            int cs = ck[tx*4 + j];
            float tmp[8];
#pragma unroll
            for (int i = 0; i < 8; i++) {
                int t = t0 + ty*8 + i;
                bool m = (s <= t) && (cs == cq[ty*8 + i]);
                tmp[i] = m ? sacc[i][j] : 0.0f;
            }
            *(float4*)&Ss[(tx*4+j)*PI + ty*8]     = make_float4(tmp[0],tmp[1],tmp[2],tmp[3]);
            *(float4*)&Ss[(tx*4+j)*PI + ty*8 + 4] = make_float4(tmp[4],tmp[5],tmp[6],tmp[7]);
        }
        __syncthreads();

#pragma unroll 8
        for (int s = 0; s < 64; s++) {
            float4 a0 = *(const float4*)&Ss[s*PI + ty*8];
            float4 a1 = *(const float4*)&Ss[s*PI + ty*8 + 4];
            float4 bv = *(const float4*)&vs[s*64 + tx*4];
            float aa[8] = {a0.x,a0.y,a0.z,a0.w,a1.x,a1.y,a1.z,a1.w};
            float bb[4] = {bv.x,bv.y,bv.z,bv.w};
#pragma unroll
            for (int i = 0; i < 8; i++)
#pragma unroll
                for (int j = 0; j < 4; j++) acc[i][j] += aa[i] * bb[j];
        }
        __syncthreads();
    }

    if (cum_t0 == 0) {
#pragma unroll
        for (int r = 0; r < 4; r++) {
            int idx = tid + r*256;
            int e = idx >> 4, c4 = (idx & 15) * 4;
            *(float4*)&ks[e*68 + c4] = *(const float4*)(state + (h*64 + e)*64 + c4);
        }
        __syncthreads();
        float sacc[8][4] = {};
#pragma unroll 8
        for (int e = 0; e < 64; e++) {
            float4 a0 = *(const float4*)&qs[e*PI + ty*8];
            float4 a1 = *(const float4*)&qs[e*PI + ty*8 + 4];
            float4 bv = *(const float4*)&ks[e*68 + tx*4];
            float aa[8] = {a0.x,a0.y,a0.z,a0.w,a1.x,a1.y,a1.z,a1.w};
            float bb[4] = {bv.x,bv.y,bv.z,bv.w};
#pragma unroll
            for (int i = 0; i < 8; i++)
#pragma unroll
                for (int j = 0; j < 4; j++) sacc[i][j] += aa[i] * bb[j];
        }
#pragma unroll
        for (int i = 0; i < 8; i++) {
            if (cq[ty*8 + i] == 0) {
#pragma unroll
                for (int j = 0; j < 4; j++) acc[i][j] += sacc[i][j];
            }
        }
    }

    float* og = g_ao + (h*T + t0)*DH;
#pragma unroll
    for (int i = 0; i < 8; i++) {
        *(float4*)&og[(ty*8+i)*DH + tx*4] = make_float4(acc[i][0],acc[i][1],acc[i][2],acc[i][3]);
    }
}

// ---------------- new_state: parallel partials + deterministic reduce ----------------
__global__ void newstate_partial_kernel() {
    __shared__ float kt[64][68];
    __shared__ float vt[64][64];
    int c = blockIdx.x;
    int h = blockIdx.y;
    int tid = threadIdx.x;
    int d = tid >> 2;
    int eg = (tid & 3) * 16;
    int cum_last = g_cum[T-1];
    int t0 = c*64;
    float* dst = &g_ns[c][h*4096 + d*64 + eg];
    if (g_cum[t0 + 63] < cum_last) {   // entirely before after_last suffix
#pragma unroll
        for (int e = 0; e < 16; e++) dst[e] = 0.0f;
        return;
    }
    float acc[16] = {};
#pragma unroll
    for (int r = 0; r < 4; r++) {
        int idx = tid + r*256;
        int tt = idx >> 4, c4 = (idx & 15) * 4;
        int t = t0 + tt;
        float m = (g_cum[t] == cum_last) ? 1.0f : 0.0f;
        float4 a = *(const float4*)(g_k + (h*T + t)*DH + c4);
        kt[tt][c4+0] = a.x*m; kt[tt][c4+1] = a.y*m;
        kt[tt][c4+2] = a.z*m; kt[tt][c4+3] = a.w*m;
        *(float4*)&vt[tt][c4] = *(const float4*)(g_v + (h*T + t)*DH + c4);
    }
    __syncthreads();
    for (int tt = 0; tt < 64; tt++) {
        float kv = kt[tt][d];
#pragma unroll
        for (int e4 = 0; e4 < 4; e4++) {
            float4 v4 = *(const float4*)&vt[tt][eg + e4*4];
            acc[e4*4+0] += kv * v4.x;
            acc[e4*4+1] += kv * v4.y;
            acc[e4*4+2] += kv * v4.z;
            acc[e4*4+3] += kv * v4.w;
        }
    }
#pragma unroll
    for (int e = 0; e < 16; e++) dst[e] = acc[e];
}

__global__ void newstate_reduce_kernel(const float* __restrict__ state,
                                       float* __restrict__ out) {
    int i = blockIdx.x * blockDim.x + threadIdx.x;  // 65536 total
    bool done_any = g_cum[T-1] > 0;
    float s = done_any ? 0.0f : state[i];
#pragma unroll
    for (int c = 0; c < 32; c++) s += g_ns[c][i];
    out[i] = s;
}

// ---------------- launch ----------------
static const int ATTN_SMEM = (64*PI + 64*68 + 64*64 + 64*PI) * 4 + (128 + 64) * 4;

extern "C" void kernel_launch(void* const* d_in, const int* in_sizes, int n_in,
                              void* d_out, int out_size) {
    const float* state  = (const float*)d_in[0];
    const float* x      = (const float*)d_in[1];
    const unsigned char* done = (const unsigned char*)d_in[2];
    const float* w_qkv  = (const float*)d_in[3];
    const float* b_qkv  = (const float*)d_in[4];
    const float* w_out  = (const float*)d_in[5];
    const float* b_out  = (const float*)d_in[6];

    float* out_state = (float*)d_out;            // H*DH*DH = 65536 elems
    float* out_x     = out_state + H*DH*DH;      // T*D elems

    cudaFuncSetAttribute(attn_kernel, cudaFuncAttributeMaxDynamicSharedMemorySize, ATTN_SMEM);

    cumsum_kernel<<<1, 256>>>(done);
    qkv_gemm_kernel<<<dim3(N3/64, T/128), 256>>>(x, w_qkv, b_qkv);
    attn_kernel<<<dim3(T/128, H), 256, ATTN_SMEM>>>(state);
    newstate_partial_kernel<<<dim3(32, H), 256>>>();
    newstate_reduce_kernel<<<64, 1024>>>(state, out_state);
    out_gemm_kernel<<<dim3(D/64, T/128), 256>>>(w_out, b_out, out_x);
}

// round 15
// speedup vs baseline: 1.3053x; 1.3053x over previous
#include <cuda_runtime.h>

#define H 16
#define T 2048
#define D 1024
#define DH 64
#define N3 3072

// ---------------- scratch (no allocations allowed) ----------------
__device__ float g_q[H*T*DH];
__device__ float g_k[H*T*DH];
__device__ float g_v[H*T*DH];
__device__ float g_ao[H*T*DH];
__device__ int   g_cum[T];
__device__ float g_ns[32][H*DH*DH];   // per-chunk R[c] = sum_{s in c, cum==E[c]} k v^T
__device__ float g_Se[32][H*DH*DH];   // per-chunk entry state (incl. carried state when E==0)

// ---------------- cumsum of done (dtype auto-detect) ----------------
__global__ void cumsum_kernel(const unsigned char* __restrict__ done) {
    __shared__ int tsum[256];
    __shared__ int s_big, s_off4;
    int tid = threadIdx.x;
    if (tid == 0) { s_big = 0; s_off4 = 0; }
    __syncthreads();
    int big = 0, off4 = 0;
    for (int i = tid; i < 2048; i += 256) {
        unsigned char bb = done[i];
        if (bb > 1) big = 1;
        if (bb != 0 && (i & 3) != 0) off4 = 1;
    }
    if (big)  atomicOr(&s_big, 1);
    if (off4) atomicOr(&s_off4, 1);
    __syncthreads();
    int mode = s_big ? 2 : (s_off4 ? 0 : 1);  // 0=bool, 1=int32, 2=float32

    int loc[8]; int s = 0;
#pragma unroll
    for (int i = 0; i < 8; i++) {
        int t = tid*8 + i;
        int v;
        if (mode == 0)      v = (done[t] != 0);
        else if (mode == 1) v = (((const int*)done)[t] != 0);
        else                v = (((const float*)done)[t] != 0.0f);
        loc[i] = v; s += v;
    }
    tsum[tid] = s; __syncthreads();
    for (int off = 1; off < 256; off <<= 1) {
        int v = (tid >= off) ? tsum[tid - off] : 0;
        __syncthreads();
        tsum[tid] += v;
        __syncthreads();
    }
    int run = (tid > 0) ? tsum[tid-1] : 0;
#pragma unroll
    for (int i = 0; i < 8; i++) { run += loc[i]; g_cum[tid*8 + i] = run; }
}

// ---------------- qkv GEMM: x(2048x1024) @ w(1024x3072) + b (round-6 known-good) ----
__global__ void qkv_gemm_kernel(const float* __restrict__ x,
                                const float* __restrict__ w,
                                const float* __restrict__ b) {
    __shared__ float As[16][68];
    __shared__ float Bs[16][64];
    int bm = blockIdx.y, bn = blockIdx.x;
    int tid = threadIdx.x;
    int tx = tid & 15, ty = tid >> 4;
    float acc[4][4] = {};
    int arow = tid >> 2, akk = (tid & 3) * 4;
    int bkk = tid >> 4, bn4 = (tid & 15) * 4;
    const float* xp = x + (bm*64 + arow)*D + akk;
    const float* wp = w + bkk*N3 + bn*64 + bn4;
    for (int kt = 0; kt < D/16; kt++) {
        float4 a = *(const float4*)(xp + kt*16);
        As[akk+0][arow] = a.x; As[akk+1][arow] = a.y;
        As[akk+2][arow] = a.z; As[akk+3][arow] = a.w;
        *(float4*)&Bs[bkk][bn4] = *(const float4*)(wp + kt*16*N3);
        __syncthreads();
#pragma unroll
        for (int kk = 0; kk < 16; kk++) {
            float4 av = *(const float4*)&As[kk][ty*4];
            float4 bv = *(const float4*)&Bs[kk][tx*4];
            float aa[4] = {av.x, av.y, av.z, av.w};
            float bb[4] = {bv.x, bv.y, bv.z, bv.w};
#pragma unroll
            for (int i = 0; i < 4; i++)
#pragma unroll
                for (int j = 0; j < 4; j++) acc[i][j] += aa[i] * bb[j];
        }
        __syncthreads();
    }
#pragma unroll
    for (int i = 0; i < 4; i++) {
        int m = bm*64 + ty*4 + i;
#pragma unroll
        for (int j = 0; j < 4; j++) {
            int n = bn*64 + tx*4 + j;
            float val = acc[i][j] + b[n];
            int qkv = n >> 10;
            int h   = (n >> 6) & 15;
            int dh  = n & 63;
            float* dst = (qkv == 0) ? g_q : ((qkv == 1) ? g_k : g_v);
            dst[(h*T + m)*DH + dh] = val;
        }
    }
}

// ---------------- R[c]: per-chunk tail kv outer product ----------------
// grid (32, H): R[c] = sum over t in chunk c with cum[t]==cum[chunk end] of k v^T
__global__ void chunk_kv_kernel() {
    __shared__ float kt[64][68];
    __shared__ float vt[64][64];
    int c = blockIdx.x;
    int h = blockIdx.y;
    int tid = threadIdx.x;
    int d = tid >> 2;
    int eg = (tid & 3) * 16;
    int t0 = c*64;
    int ctail = g_cum[t0 + 63];
    float acc[16] = {};
#pragma unroll
    for (int r = 0; r < 4; r++) {
        int idx = tid + r*256;
        int tt = idx >> 4, c4 = (idx & 15) * 4;
        int t = t0 + tt;
        float m = (g_cum[t] == ctail) ? 1.0f : 0.0f;
        float4 a = *(const float4*)(g_k + (h*T + t)*DH + c4);
        kt[tt][c4+0] = a.x*m; kt[tt][c4+1] = a.y*m;
        kt[tt][c4+2] = a.z*m; kt[tt][c4+3] = a.w*m;
        *(float4*)&vt[tt][c4] = *(const float4*)(g_v + (h*T + t)*DH + c4);
    }
    __syncthreads();
    for (int tt = 0; tt < 64; tt++) {
        float kv = kt[tt][d];
#pragma unroll
        for (int e4 = 0; e4 < 4; e4++) {
            float4 v4 = *(const float4*)&vt[tt][eg + e4*4];
            acc[e4*4+0] += kv * v4.x;
            acc[e4*4+1] += kv * v4.y;
            acc[e4*4+2] += kv * v4.z;
            acc[e4*4+3] += kv * v4.w;
        }
    }
    float* dst = &g_ns[c][h*4096 + d*64 + eg];
#pragma unroll
    for (int e = 0; e < 16; e++) dst[e] = acc[e];
}

// ---------------- segmented scan over chunks ----------------
// grid (H, 4), 256 threads; each thread owns 4 floats of the 64x64 state.
// S_last recurrence: S = (E[c]!=E[c-1]) ? R[c] : S + R[c].
// Writes S_entry_eff[c] = S_last[c-1] + (E[c-1]==0 ? state : 0), and final new_state.
__global__ void state_scan_kernel(const float* __restrict__ state,
                                  float* __restrict__ out_state) {
    int h = blockIdx.x, cg = blockIdx.y;
    int base = h*4096 + cg*1024 + threadIdx.x*4;
    float4 st = *(const float4*)(state + base);
    float4 S = make_float4(0.f, 0.f, 0.f, 0.f);
    int Eprev = 0;
    for (int c = 0; c < 32; c++) {
        float4 w = S;
        if (Eprev == 0) { w.x += st.x; w.y += st.y; w.z += st.z; w.w += st.w; }
        *(float4*)&g_Se[c][base] = w;
        int Ec = g_cum[c*64 + 63];
        float4 R = *(const float4*)&g_ns[c][base];
        if (Ec != Eprev) { S = R; }
        else { S.x += R.x; S.y += R.y; S.z += R.z; S.w += R.w; }
        Eprev = Ec;
    }
    float4 w = S;
    if (Eprev == 0) { w.x += st.x; w.y += st.y; w.z += st.z; w.w += st.w; }
    *(float4*)(out_state + base) = w;
}

// ---------------- chunked attention ----------------
// grid (32, H), 256 threads. Per chunk: local masked q k^T @ v + gated q @ S_entry.
__global__ void chunk_attn_kernel() {
    extern __shared__ float sm[];
    float* qs = sm;             // [64][68]  q transposed [d][t]
    float* ks = qs + 64*68;     // [64][68]  k transposed [d][s]; reused for Se [d][e]
    float* vs = ks + 64*68;     // [64][64]  [s][e]
    float* Ss = vs + 64*64;     // [64][68]  masked scores transposed [s][t]
    int*   cq = (int*)(Ss + 64*68);   // [64]

    int c = blockIdx.x, h = blockIdx.y;
    int t0 = c*64;
    int tid = threadIdx.x;
    int tx = tid & 15, ty = tid >> 4;

    const float* qg = g_q + (h*T + t0)*DH;
    const float* kg = g_k + (h*T + t0)*DH;
    const float* vg = g_v + (h*T + t0)*DH;
#pragma unroll
    for (int r = 0; r < 4; r++) {
        int idx = tid + r*256;             // 1024 float4 groups: 64 rows x 16
        int row = idx >> 4, c4 = (idx & 15) * 4;
        float4 a = *(const float4*)(qg + row*DH + c4);
        qs[(c4+0)*68 + row] = a.x; qs[(c4+1)*68 + row] = a.y;
        qs[(c4+2)*68 + row] = a.z; qs[(c4+3)*68 + row] = a.w;
        float4 bk = *(const float4*)(kg + row*DH + c4);
        ks[(c4+0)*68 + row] = bk.x; ks[(c4+1)*68 + row] = bk.y;
        ks[(c4+2)*68 + row] = bk.z; ks[(c4+3)*68 + row] = bk.w;
        *(float4*)&vs[row*64 + c4] = *(const float4*)(vg + row*DH + c4);
    }
    if (tid < 64) cq[tid] = g_cum[t0 + tid];
    __syncthreads();

    int prevE = (c == 0) ? 0 : g_cum[t0 - 1];

    // phase A: sacc[t][s] = sum_d q[t][d] k[s][d]
    float sacc[4][4] = {};
#pragma unroll 8
    for (int d = 0; d < 64; d++) {
        float4 av = *(const float4*)&qs[d*68 + ty*4];
        float4 bv = *(const float4*)&ks[d*68 + tx*4];
        float aa[4] = {av.x, av.y, av.z, av.w};
        float bb[4] = {bv.x, bv.y, bv.z, bv.w};
#pragma unroll
        for (int i = 0; i < 4; i++)
#pragma unroll
            for (int j = 0; j < 4; j++) sacc[i][j] += aa[i] * bb[j];
    }
    // mask & store transposed
#pragma unroll
    for (int j = 0; j < 4; j++) {
        int s_l = tx*4 + j;
        int cs  = cq[s_l];
        float tmp[4];
#pragma unroll
        for (int i = 0; i < 4; i++) {
            int t_l = ty*4 + i;
            bool m = (s_l <= t_l) && (cs == cq[t_l]);
            tmp[i] = m ? sacc[i][j] : 0.0f;
        }
        *(float4*)&Ss[s_l*68 + ty*4] = make_float4(tmp[0], tmp[1], tmp[2], tmp[3]);
    }
    __syncthreads();

    // overlap: load Se into ks (ks no longer needed); consumed after next sync
    const float* seg = &g_Se[c][h*4096];
#pragma unroll
    for (int r = 0; r < 4; r++) {
        int idx = tid + r*256;             // 1024 float4 groups: 64 d x 16
        int dd = idx >> 4, e4 = (idx & 15) * 4;
        *(float4*)&ks[dd*68 + e4] = *(const float4*)(seg + dd*64 + e4);
    }

    // phase B1: acc[t][e] = sum_s Ss[s][t] * v[s][e]
    float acc[4][4] = {};
#pragma unroll 8
    for (int s = 0; s < 64; s++) {
        float4 av = *(const float4*)&Ss[s*68 + ty*4];
        float4 bv = *(const float4*)&vs[s*64 + tx*4];
        float aa[4] = {av.x, av.y, av.z, av.w};
        float bb[4] = {bv.x, bv.y, bv.z, bv.w};
#pragma unroll
        for (int i = 0; i < 4; i++)
#pragma unroll
            for (int j = 0; j < 4; j++) acc[i][j] += aa[i] * bb[j];
    }
    __syncthreads();   // Se stores visible

    // phase B2: gated entry-state term: sum_d q[t][d] * Se[d][e]
    float sacc2[4][4] = {};
#pragma unroll 8
    for (int d = 0; d < 64; d++) {
        float4 av = *(const float4*)&qs[d*68 + ty*4];
        float4 bv = *(const float4*)&ks[d*68 + tx*4];
        float aa[4] = {av.x, av.y, av.z, av.w};
        float bb[4] = {bv.x, bv.y, bv.z, bv.w};
#pragma unroll
        for (int i = 0; i < 4; i++)
#pragma unroll
            for (int j = 0; j < 4; j++) sacc2[i][j] += aa[i] * bb[j];
    }
#pragma unroll
    for (int i = 0; i < 4; i++) {
        if (cq[ty*4 + i] == prevE) {
#pragma unroll
            for (int j = 0; j < 4; j++) acc[i][j] += sacc2[i][j];
        }
    }

    float* og = g_ao + (h*T + t0)*DH;
#pragma unroll
    for (int i = 0; i < 4; i++) {
        *(float4*)&og[(ty*4+i)*DH + tx*4] = make_float4(acc[i][0], acc[i][1], acc[i][2], acc[i][3]);
    }
}

// ---------------- out projection: ao(T x D, head-chunked) @ w_out + b_out ----------------
__global__ void out_gemm_kernel(const float* __restrict__ w,
                                const float* __restrict__ b,
                                float* __restrict__ xout) {
    __shared__ float As[16][68];
    __shared__ float Bs[16][64];
    int bm = blockIdx.y, bn = blockIdx.x;
    int tid = threadIdx.x;
    int tx = tid & 15, ty = tid >> 4;
    float acc[4][4] = {};
    int arow = tid >> 2, akk = (tid & 3) * 4;
    int bkk = tid >> 4, bn4 = (tid & 15) * 4;
    int m = bm*64 + arow;
    for (int kt = 0; kt < D/16; kt++) {
        int k  = kt*16 + akk;
        int hh = k >> 6, dh = k & 63;
        float4 a = *(const float4*)(g_ao + (hh*T + m)*DH + dh);
        As[akk+0][arow] = a.x; As[akk+1][arow] = a.y;
        As[akk+2][arow] = a.z; As[akk+3][arow] = a.w;
        *(float4*)&Bs[bkk][bn4] = *(const float4*)(w + (kt*16 + bkk)*D + bn*64 + bn4);
        __syncthreads();
#pragma unroll
        for (int kk = 0; kk < 16; kk++) {
            float4 av = *(const float4*)&As[kk][ty*4];
            float4 bv = *(const float4*)&Bs[kk][tx*4];
            float aa[4] = {av.x, av.y, av.z, av.w};
            float bb[4] = {bv.x, bv.y, bv.z, bv.w};
#pragma unroll
            for (int i = 0; i < 4; i++)
#pragma unroll
                for (int j = 0; j < 4; j++) acc[i][j] += aa[i] * bb[j];
        }
        __syncthreads();
    }
#pragma unroll
    for (int i = 0; i < 4; i++) {
        int mm = bm*64 + ty*4 + i;
#pragma unroll
        for (int j = 0; j < 4; j++) {
            int n = bn*64 + tx*4 + j;
            xout[mm*D + n] = acc[i][j] + b[n];
        }
    }
}

// ---------------- launch ----------------
static const int CA_SMEM = (64*68 + 64*68 + 64*64 + 64*68 + 64) * 4;

extern "C" void kernel_launch(void* const* d_in, const int* in_sizes, int n_in,
                              void* d_out, int out_size) {
    const float* state  = (const float*)d_in[0];
    const float* x      = (const float*)d_in[1];
    const unsigned char* done = (const unsigned char*)d_in[2];
    const float* w_qkv  = (const float*)d_in[3];
    const float* b_qkv  = (const float*)d_in[4];
    const float* w_out  = (const float*)d_in[5];
    const float* b_out  = (const float*)d_in[6];

    float* out_state = (float*)d_out;            // H*DH*DH = 65536 elems
    float* out_x     = out_state + H*DH*DH;      // T*D elems

    cudaFuncSetAttribute(chunk_attn_kernel, cudaFuncAttributeMaxDynamicSharedMemorySize, CA_SMEM);

    cumsum_kernel<<<1, 256>>>(done);
    qkv_gemm_kernel<<<dim3(N3/64, T/64), 256>>>(x, w_qkv, b_qkv);
    chunk_kv_kernel<<<dim3(32, H), 256>>>();
    state_scan_kernel<<<dim3(H, 4), 256>>>(state, out_state);
    chunk_attn_kernel<<<dim3(32, H), 256, CA_SMEM>>>();
    out_gemm_kernel<<<dim3(D/64, T/64), 256>>>(w_out, b_out, out_x);
}

// round 16
// speedup vs baseline: 1.8646x; 1.4285x over previous
#include <cuda_runtime.h>
#include <cuda_bf16.h>
#include <cstdint>

#define H 16
#define T 2048
#define D 1024
#define DH 64
#define N3 3072

// ---------------- scratch (no allocations allowed) ----------------
__device__ float g_q[H*T*DH];
__device__ float g_k[H*T*DH];
__device__ float g_v[H*T*DH];
__device__ float g_ao[H*T*DH];
__device__ int   g_cum[T];
__device__ float g_ns[32][H*DH*DH];   // per-chunk R[c]
__device__ float g_Se[32][H*DH*DH];   // per-chunk entry state
__device__ __nv_bfloat16 g_xs0[T*D],  g_xs1[T*D];    // x  2-way bf16 split [T][D]
__device__ __nv_bfloat16 g_ws0[N3*D], g_ws1[N3*D];   // w_qkv^T 2-way split [N3][D]

// ---------------- mma/ldmatrix helpers ----------------
__device__ __forceinline__ void ldsm4(unsigned* r, const void* p) {
    unsigned addr = (unsigned)__cvta_generic_to_shared(p);
    asm volatile("ldmatrix.sync.aligned.m8n8.x4.shared.b16 {%0,%1,%2,%3}, [%4];"
        : "=r"(r[0]), "=r"(r[1]), "=r"(r[2]), "=r"(r[3]) : "r"(addr));
}
__device__ __forceinline__ void mma_bf16(float* c, const unsigned* a, unsigned b0, unsigned b1) {
    asm volatile("mma.sync.aligned.m16n8k16.row.col.f32.bf16.bf16.f32 "
        "{%0,%1,%2,%3},{%4,%5,%6,%7},{%8,%9},{%0,%1,%2,%3};"
        : "+f"(c[0]), "+f"(c[1]), "+f"(c[2]), "+f"(c[3])
        : "r"(a[0]), "r"(a[1]), "r"(a[2]), "r"(a[3]), "r"(b0), "r"(b1));
}

// ---------------- cumsum of done (dtype auto-detect) ----------------
__global__ void cumsum_kernel(const unsigned char* __restrict__ done) {
    __shared__ int tsum[256];
    __shared__ int s_big, s_off4;
    int tid = threadIdx.x;
    if (tid == 0) { s_big = 0; s_off4 = 0; }
    __syncthreads();
    int big = 0, off4 = 0;
    for (int i = tid; i < 2048; i += 256) {
        unsigned char bb = done[i];
        if (bb > 1) big = 1;
        if (bb != 0 && (i & 3) != 0) off4 = 1;
    }
    if (big)  atomicOr(&s_big, 1);
    if (off4) atomicOr(&s_off4, 1);
    __syncthreads();
    int mode = s_big ? 2 : (s_off4 ? 0 : 1);  // 0=bool, 1=int32, 2=float32

    int loc[8]; int s = 0;
#pragma unroll
    for (int i = 0; i < 8; i++) {
        int t = tid*8 + i;
        int v;
        if (mode == 0)      v = (done[t] != 0);
        else if (mode == 1) v = (((const int*)done)[t] != 0);
        else                v = (((const float*)done)[t] != 0.0f);
        loc[i] = v; s += v;
    }
    tsum[tid] = s; __syncthreads();
    for (int off = 1; off < 256; off <<= 1) {
        int v = (tid >= off) ? tsum[tid - off] : 0;
        __syncthreads();
        tsum[tid] += v;
        __syncthreads();
    }
    int run = (tid > 0) ? tsum[tid-1] : 0;
#pragma unroll
    for (int i = 0; i < 8; i++) { run += loc[i]; g_cum[tid*8 + i] = run; }
}

// ---------------- bf16 2-way split of x ----------------
__global__ void split_x_kernel(const float* __restrict__ x) {
    int i4 = blockIdx.x * blockDim.x + threadIdx.x;   // 524288 threads, 4 floats each
    float4 v = ((const float4*)x)[i4];
    float a[4] = {v.x, v.y, v.z, v.w};
    __nv_bfloat16 h0[4], h1[4];
#pragma unroll
    for (int e = 0; e < 4; e++) {
        h0[e] = __float2bfloat16(a[e]);
        h1[e] = __float2bfloat16(a[e] - __bfloat162float(h0[e]));
    }
    __nv_bfloat162* p0 = (__nv_bfloat162*)g_xs0;
    __nv_bfloat162* p1 = (__nv_bfloat162*)g_xs1;
    p0[i4*2]   = __nv_bfloat162(h0[0], h0[1]); p0[i4*2+1] = __nv_bfloat162(h0[2], h0[3]);
    p1[i4*2]   = __nv_bfloat162(h1[0], h1[1]); p1[i4*2+1] = __nv_bfloat162(h1[2], h1[3]);
}

// ---------------- transpose + split of w_qkv: [K=1024][N=3072] -> ws[n][k] ----------------
__global__ void split_wt_kernel(const float* __restrict__ w) {
    __shared__ float t[32][33];
    int n0 = blockIdx.x * 32, k0 = blockIdx.y * 32;
    int tx = threadIdx.x & 31, ty = threadIdx.x >> 5;   // 256 threads: 32x8
#pragma unroll
    for (int r = 0; r < 4; r++)
        t[ty + 8*r][tx] = w[(k0 + ty + 8*r)*N3 + n0 + tx];
    __syncthreads();
#pragma unroll
    for (int r = 0; r < 4; r++) {
        int nn = ty + 8*r, kk = tx;
        float a = t[kk][nn];
        __nv_bfloat16 b0 = __float2bfloat16(a);
        __nv_bfloat16 b1 = __float2bfloat16(a - __bfloat162float(b0));
        int o = (n0 + nn)*D + k0 + kk;
        g_ws0[o] = b0; g_ws1[o] = b1;
    }
}

// ---------------- qkv GEMM via bf16 mma.sync (3-term split) ----------------
// Block 128(M) x 128(N), 8 warps (warp 32x64), K chunks of 32. smem pitch 40 bf16.
#define SP 40
__global__ void __launch_bounds__(256, 1) qkv_mma_kernel(const float* __restrict__ bias) {
    __shared__ __nv_bfloat16 As0[128*SP], As1[128*SP], Bs0[128*SP], Bs1[128*SP];
    int tid = threadIdx.x;
    int lane = tid & 31, warp = tid >> 5;
    int bn = blockIdx.x, bm = blockIdx.y;
    int wm = (warp & 3) * 32, wn = (warp >> 2) * 64;

    float acc[2][8][4] = {};   // [mt][n8 tile][frag]

    int a_r = (lane & 7) + ((lane >> 3) & 1) * 8;   // A ldmatrix row-in-tile
    int a_c = (lane >> 4) * 8;                      // A ldmatrix col-in-tile
    int b_r = (lane & 7) + (lane >> 4) * 8;         // B ldmatrix row-in-tile
    int b_c = ((lane >> 3) & 1) * 8;                // B ldmatrix col-in-tile

    for (int kt = 0; kt < 32; kt++) {
        // stage 4 arrays: 128 rows x 32 bf16 each (row = idx>>2, seg = idx&3)
#pragma unroll
        for (int r = 0; r < 2; r++) {
            int idx = tid + r*256;
            int row = idx >> 2, seg = idx & 3;
            int gsrc_a = (bm*128 + row)*D + kt*32 + seg*8;
            int gsrc_b = (bn*128 + row)*D + kt*32 + seg*8;
            int dsto = row*SP + seg*8;
            *(uint4*)(As0 + dsto) = *(const uint4*)(g_xs0 + gsrc_a);
            *(uint4*)(As1 + dsto) = *(const uint4*)(g_xs1 + gsrc_a);
            *(uint4*)(Bs0 + dsto) = *(const uint4*)(g_ws0 + gsrc_b);
            *(uint4*)(Bs1 + dsto) = *(const uint4*)(g_ws1 + gsrc_b);
        }
        __syncthreads();
#pragma unroll
        for (int ks = 0; ks < 2; ks++) {
            unsigned a0f[2][4], a1f[2][4], b0f[4][4], b1f[4][4];
#pragma unroll
            for (int mt = 0; mt < 2; mt++) {
                int off = (wm + mt*16 + a_r)*SP + ks*16 + a_c;
                ldsm4(a0f[mt], As0 + off);
                ldsm4(a1f[mt], As1 + off);
            }
#pragma unroll
            for (int nb = 0; nb < 4; nb++) {
                int off = (wn + nb*16 + b_r)*SP + ks*16 + b_c;
                ldsm4(b0f[nb], Bs0 + off);
                ldsm4(b1f[nb], Bs1 + off);
            }
#pragma unroll
            for (int mt = 0; mt < 2; mt++)
#pragma unroll
                for (int nb = 0; nb < 4; nb++) {
                    float* cLo = acc[mt][nb*2+0];
                    float* cHi = acc[mt][nb*2+1];
                    mma_bf16(cLo, a0f[mt], b0f[nb][0], b0f[nb][1]);
                    mma_bf16(cLo, a0f[mt], b1f[nb][0], b1f[nb][1]);
                    mma_bf16(cLo, a1f[mt], b0f[nb][0], b0f[nb][1]);
                    mma_bf16(cHi, a0f[mt], b0f[nb][2], b0f[nb][3]);
                    mma_bf16(cHi, a0f[mt], b1f[nb][2], b1f[nb][3]);
                    mma_bf16(cHi, a1f[mt], b0f[nb][2], b0f[nb][3]);
                }
        }
        __syncthreads();
    }

    // epilogue: frag (mt, nb, half): rows m0, m0+8; cols n0, n0+1
#pragma unroll
    for (int mt = 0; mt < 2; mt++) {
        int m0 = bm*128 + wm + mt*16 + (lane >> 2);
#pragma unroll
        for (int nb = 0; nb < 4; nb++)
#pragma unroll
            for (int half = 0; half < 2; half++) {
                int n0 = bn*128 + wn + nb*16 + half*8 + 2*(lane & 3);
                const float* C = acc[mt][nb*2+half];
#pragma unroll
                for (int e = 0; e < 4; e++) {
                    int m = m0 + (e >> 1) * 8;
                    int n = n0 + (e & 1);
                    float val = C[e] + __ldg(bias + n);
                    int qkv = n >> 10;
                    int h   = (n >> 6) & 15;
                    int dh  = n & 63;
                    float* dst = (qkv == 0) ? g_q : ((qkv == 1) ? g_k : g_v);
                    dst[(h*T + m)*DH + dh] = val;
                }
            }
    }
}

// ---------------- R[c]: per-chunk tail kv outer product ----------------
__global__ void chunk_kv_kernel() {
    __shared__ float kt[64][68];
    __shared__ float vt[64][64];
    int c = blockIdx.x;
    int h = blockIdx.y;
    int tid = threadIdx.x;
    int d = tid >> 2;
    int eg = (tid & 3) * 16;
    int t0 = c*64;
    int ctail = g_cum[t0 + 63];
    float acc[16] = {};
#pragma unroll
    for (int r = 0; r < 4; r++) {
        int idx = tid + r*256;
        int tt = idx >> 4, c4 = (idx & 15) * 4;
        int t = t0 + tt;
        float m = (g_cum[t] == ctail) ? 1.0f : 0.0f;
        float4 a = *(const float4*)(g_k + (h*T + t)*DH + c4);
        kt[tt][c4+0] = a.x*m; kt[tt][c4+1] = a.y*m;
        kt[tt][c4+2] = a.z*m; kt[tt][c4+3] = a.w*m;
        *(float4*)&vt[tt][c4] = *(const float4*)(g_v + (h*T + t)*DH + c4);
    }
    __syncthreads();
    for (int tt = 0; tt < 64; tt++) {
        float kv = kt[tt][d];
#pragma unroll
        for (int e4 = 0; e4 < 4; e4++) {
            float4 v4 = *(const float4*)&vt[tt][eg + e4*4];
            acc[e4*4+0] += kv * v4.x;
            acc[e4*4+1] += kv * v4.y;
            acc[e4*4+2] += kv * v4.z;
            acc[e4*4+3] += kv * v4.w;
        }
    }
    float* dst = &g_ns[c][h*4096 + d*64 + eg];
#pragma unroll
    for (int e = 0; e < 16; e++) dst[e] = acc[e];
}

// ---------------- segmented scan over chunks ----------------
__global__ void state_scan_kernel(const float* __restrict__ state,
                                  float* __restrict__ out_state) {
    int h = blockIdx.x, cg = blockIdx.y;
    int base = h*4096 + cg*1024 + threadIdx.x*4;
    float4 st = *(const float4*)(state + base);
    float4 S = make_float4(0.f, 0.f, 0.f, 0.f);
    int Eprev = 0;
    for (int c = 0; c < 32; c++) {
        float4 w = S;
        if (Eprev == 0) { w.x += st.x; w.y += st.y; w.z += st.z; w.w += st.w; }
        *(float4*)&g_Se[c][base] = w;
        int Ec = g_cum[c*64 + 63];
        float4 R = *(const float4*)&g_ns[c][base];
        if (Ec != Eprev) { S = R; }
        else { S.x += R.x; S.y += R.y; S.z += R.z; S.w += R.w; }
        Eprev = Ec;
    }
    float4 w = S;
    if (Eprev == 0) { w.x += st.x; w.y += st.y; w.z += st.z; w.w += st.w; }
    *(float4*)(out_state + base) = w;
}

// ---------------- chunked attention ----------------
__global__ void chunk_attn_kernel() {
    extern __shared__ float sm[];
    float* qs = sm;             // [64][68]  q transposed [d][t]
    float* ks = qs + 64*68;     // [64][68]  k transposed [d][s]; reused for Se [d][e]
    float* vs = ks + 64*68;     // [64][64]  [s][e]
    float* Ss = vs + 64*64;     // [64][68]  masked scores transposed [s][t]
    int*   cq = (int*)(Ss + 64*68);   // [64]

    int c = blockIdx.x, h = blockIdx.y;
    int t0 = c*64;
    int tid = threadIdx.x;
    int tx = tid & 15, ty = tid >> 4;

    const float* qg = g_q + (h*T + t0)*DH;
    const float* kg = g_k + (h*T + t0)*DH;
    const float* vg = g_v + (h*T + t0)*DH;
#pragma unroll
    for (int r = 0; r < 4; r++) {
        int idx = tid + r*256;             // 1024 float4 groups: 64 rows x 16
        int row = idx >> 4, c4 = (idx & 15) * 4;
        float4 a = *(const float4*)(qg + row*DH + c4);
        qs[(c4+0)*68 + row] = a.x; qs[(c4+1)*68 + row] = a.y;
        qs[(c4+2)*68 + row] = a.z; qs[(c4+3)*68 + row] = a.w;
        float4 bk = *(const float4*)(kg + row*DH + c4);
        ks[(c4+0)*68 + row] = bk.x; ks[(c4+1)*68 + row] = bk.y;
        ks[(c4+2)*68 + row] = bk.z; ks[(c4+3)*68 + row] = bk.w;
        *(float4*)&vs[row*64 + c4] = *(const float4*)(vg + row*DH + c4);
    }
    if (tid < 64) cq[tid] = g_cum[t0 + tid];
    __syncthreads();

    int prevE = (c == 0) ? 0 : g_cum[t0 - 1];

    // phase A: sacc[t][s] = sum_d q[t][d] k[s][d]
    float sacc[4][4] = {};
#pragma unroll 8
    for (int d = 0; d < 64; d++) {
        float4 av = *(const float4*)&qs[d*68 + ty*4];
        float4 bv = *(const float4*)&ks[d*68 + tx*4];
        float aa[4] = {av.x, av.y, av.z, av.w};
        float bb[4] = {bv.x, bv.y, bv.z, bv.w};
#pragma unroll
        for (int i = 0; i < 4; i++)
#pragma unroll
            for (int j = 0; j < 4; j++) sacc[i][j] += aa[i] * bb[j];
    }
    // mask & store transposed
#pragma unroll
    for (int j = 0; j < 4; j++) {
        int s_l = tx*4 + j;
        int cs  = cq[s_l];
        float tmp[4];
#pragma unroll
        for (int i = 0; i < 4; i++) {
            int t_l = ty*4 + i;
            bool m = (s_l <= t_l) && (cs == cq[t_l]);
            tmp[i] = m ? sacc[i][j] : 0.0f;
        }
        *(float4*)&Ss[s_l*68 + ty*4] = make_float4(tmp[0], tmp[1], tmp[2], tmp[3]);
    }
    __syncthreads();

    // overlap: load Se into ks
    const float* seg = &g_Se[c][h*4096];
#pragma unroll
    for (int r = 0; r < 4; r++) {
        int idx = tid + r*256;
        int dd = idx >> 4, e4 = (idx & 15) * 4;
        *(float4*)&ks[dd*68 + e4] = *(const float4*)(seg + dd*64 + e4);
    }

    // phase B1: acc[t][e] = sum_s Ss[s][t] * v[s][e]
    float acc[4][4] = {};
#pragma unroll 8
    for (int s = 0; s < 64; s++) {
        float4 av = *(const float4*)&Ss[s*68 + ty*4];
        float4 bv = *(const float4*)&vs[s*64 + tx*4];
        float aa[4] = {av.x, av.y, av.z, av.w};
        float bb[4] = {bv.x, bv.y, bv.z, bv.w};
#pragma unroll
        for (int i = 0; i < 4; i++)
#pragma unroll
            for (int j = 0; j < 4; j++) acc[i][j] += aa[i] * bb[j];
    }
    __syncthreads();   // Se stores visible

    // phase B2: gated entry-state term
    float sacc2[4][4] = {};
#pragma unroll 8
    for (int d = 0; d < 64; d++) {
        float4 av = *(const float4*)&qs[d*68 + ty*4];
        float4 bv = *(const float4*)&ks[d*68 + tx*4];
        float aa[4] = {av.x, av.y, av.z, av.w};
        float bb[4] = {bv.x, bv.y, bv.z, bv.w};
#pragma unroll
        for (int i = 0; i < 4; i++)
#pragma unroll
            for (int j = 0; j < 4; j++) sacc2[i][j] += aa[i] * bb[j];
    }
#pragma unroll
    for (int i = 0; i < 4; i++) {
        if (cq[ty*4 + i] == prevE) {
#pragma unroll
            for (int j = 0; j < 4; j++) acc[i][j] += sacc2[i][j];
        }
    }

    float* og = g_ao + (h*T + t0)*DH;
#pragma unroll
    for (int i = 0; i < 4; i++) {
        *(float4*)&og[(ty*4+i)*DH + tx*4] = make_float4(acc[i][0], acc[i][1], acc[i][2], acc[i][3]);
    }
}

// ---------------- out projection: ao(T x D, head-chunked) @ w_out + b_out ----------------
__global__ void out_gemm_kernel(const float* __restrict__ w,
                                const float* __restrict__ b,
                                float* __restrict__ xout) {
    __shared__ float As[16][68];
    __shared__ float Bs[16][64];
    int bm = blockIdx.y, bn = blockIdx.x;
    int tid = threadIdx.x;
    int tx = tid & 15, ty = tid >> 4;
    float acc[4][4] = {};
    int arow = tid >> 2, akk = (tid & 3) * 4;
    int bkk = tid >> 4, bn4 = (tid & 15) * 4;
    int m = bm*64 + arow;
    for (int kt = 0; kt < D/16; kt++) {
        int k  = kt*16 + akk;
        int hh = k >> 6, dh = k & 63;
        float4 a = *(const float4*)(g_ao + (hh*T + m)*DH + dh);
        As[akk+0][arow] = a.x; As[akk+1][arow] = a.y;
        As[akk+2][arow] = a.z; As[akk+3][arow] = a.w;
        *(float4*)&Bs[bkk][bn4] = *(const float4*)(w + (kt*16 + bkk)*D + bn*64 + bn4);
        __syncthreads();
#pragma unroll
        for (int kk = 0; kk < 16; kk++) {
            float4 av = *(const float4*)&As[kk][ty*4];
            float4 bv = *(const float4*)&Bs[kk][tx*4];
            float aa[4] = {av.x, av.y, av.z, av.w};
            float bb[4] = {bv.x, bv.y, bv.z, bv.w};
#pragma unroll
            for (int i = 0; i < 4; i++)
#pragma unroll
                for (int j = 0; j < 4; j++) acc[i][j] += aa[i] * bb[j];
        }
        __syncthreads();
    }
#pragma unroll
    for (int i = 0; i < 4; i++) {
        int mm = bm*64 + ty*4 + i;
#pragma unroll
        for (int j = 0; j < 4; j++) {
            int n = bn*64 + tx*4 + j;
            xout[mm*D + n] = acc[i][j] + b[n];
        }
    }
}

// ---------------- launch ----------------
static const int CA_SMEM = (64*68 + 64*68 + 64*64 + 64*68 + 64) * 4;

extern "C" void kernel_launch(void* const* d_in, const int* in_sizes, int n_in,
                              void* d_out, int out_size) {
    const float* state  = (const float*)d_in[0];
    const float* x      = (const float*)d_in[1];
    const unsigned char* done = (const unsigned char*)d_in[2];
    const float* w_qkv  = (const float*)d_in[3];
    const float* b_qkv  = (const float*)d_in[4];
    const float* w_out  = (const float*)d_in[5];
    const float* b_out  = (const float*)d_in[6];

    float* out_state = (float*)d_out;            // H*DH*DH = 65536 elems
    float* out_x     = out_state + H*DH*DH;      // T*D elems

    cudaFuncSetAttribute(chunk_attn_kernel, cudaFuncAttributeMaxDynamicSharedMemorySize, CA_SMEM);

    cumsum_kernel<<<1, 256>>>(done);
    split_x_kernel<<<2048, 256>>>(x);
    split_wt_kernel<<<dim3(N3/32, D/32), 256>>>(w_qkv);
    qkv_mma_kernel<<<dim3(N3/128, T/128), 256>>>(b_qkv);
    chunk_kv_kernel<<<dim3(32, H), 256>>>();
    state_scan_kernel<<<dim3(H, 4), 256>>>(state, out_state);
    chunk_attn_kernel<<<dim3(32, H), 256, CA_SMEM>>>();
    out_gemm_kernel<<<dim3(D/64, T/64), 256>>>(w_out, b_out, out_x);
}

// round 17
// speedup vs baseline: 2.6441x; 1.4180x over previous
#include <cuda_runtime.h>
#include <cuda_bf16.h>
#include <cstdint>

#define H 16
#define T 2048
#define D 1024
#define DH 64
#define N3 3072

// ---------------- scratch (no allocations allowed) ----------------
__device__ float g_q[H*T*DH];
__device__ float g_k[H*T*DH];
__device__ float g_v[H*T*DH];
__device__ float g_ao[H*T*DH];
__device__ int   g_cum[T];
__device__ float g_ns[32][H*DH*DH];   // per-chunk R[c]
__device__ float g_Se[32][H*DH*DH];   // per-chunk entry state
__device__ __nv_bfloat16 g_xs0[T*D],  g_xs1[T*D];    // x  2-way bf16 split [T][D]
__device__ __nv_bfloat16 g_ws0[N3*D], g_ws1[N3*D];   // w_qkv^T 2-way split [N3][D]
__device__ __nv_bfloat16 g_as0[T*D],  g_as1[T*D];    // ao 2-way split [T][D]
__device__ __nv_bfloat16 g_wo0[D*D],  g_wo1[D*D];    // w_out^T 2-way split [D][D]

// ---------------- mma/ldmatrix/cp.async helpers ----------------
__device__ __forceinline__ void ldsm4(unsigned* r, const void* p) {
    unsigned addr = (unsigned)__cvta_generic_to_shared(p);
    asm volatile("ldmatrix.sync.aligned.m8n8.x4.shared.b16 {%0,%1,%2,%3}, [%4];"
        : "=r"(r[0]), "=r"(r[1]), "=r"(r[2]), "=r"(r[3]) : "r"(addr));
}
__device__ __forceinline__ void mma_bf16(float* c, const unsigned* a, unsigned b0, unsigned b1) {
    asm volatile("mma.sync.aligned.m16n8k16.row.col.f32.bf16.bf16.f32 "
        "{%0,%1,%2,%3},{%4,%5,%6,%7},{%8,%9},{%0,%1,%2,%3};"
        : "+f"(c[0]), "+f"(c[1]), "+f"(c[2]), "+f"(c[3])
        : "r"(a[0]), "r"(a[1]), "r"(a[2]), "r"(a[3]), "r"(b0), "r"(b1));
}
__device__ __forceinline__ void cpa16(void* dst, const void* src) {
    unsigned d = (unsigned)__cvta_generic_to_shared(dst);
    asm volatile("cp.async.ca.shared.global [%0], [%1], 16;" :: "r"(d), "l"(src));
}
__device__ __forceinline__ void cpa_commit() { asm volatile("cp.async.commit_group;"); }
__device__ __forceinline__ void cpa_wait1()  { asm volatile("cp.async.wait_group 1;"); }
__device__ __forceinline__ void cpa_wait0()  { asm volatile("cp.async.wait_group 0;"); }

// ---------------- cumsum of done (dtype auto-detect) ----------------
__global__ void cumsum_kernel(const unsigned char* __restrict__ done) {
    __shared__ int tsum[256];
    __shared__ int s_big, s_off4;
    int tid = threadIdx.x;
    if (tid == 0) { s_big = 0; s_off4 = 0; }
    __syncthreads();
    int big = 0, off4 = 0;
    for (int i = tid; i < 2048; i += 256) {
        unsigned char bb = done[i];
        if (bb > 1) big = 1;
        if (bb != 0 && (i & 3) != 0) off4 = 1;
    }
    if (big)  atomicOr(&s_big, 1);
    if (off4) atomicOr(&s_off4, 1);
    __syncthreads();
    int mode = s_big ? 2 : (s_off4 ? 0 : 1);  // 0=bool, 1=int32, 2=float32

    int loc[8]; int s = 0;
#pragma unroll
    for (int i = 0; i < 8; i++) {
        int t = tid*8 + i;
        int v;
        if (mode == 0)      v = (done[t] != 0);
        else if (mode == 1) v = (((const int*)done)[t] != 0);
        else                v = (((const float*)done)[t] != 0.0f);
        loc[i] = v; s += v;
    }
    tsum[tid] = s; __syncthreads();
    for (int off = 1; off < 256; off <<= 1) {
        int v = (tid >= off) ? tsum[tid - off] : 0;
        __syncthreads();
        tsum[tid] += v;
        __syncthreads();
    }
    int run = (tid > 0) ? tsum[tid-1] : 0;
#pragma unroll
    for (int i = 0; i < 8; i++) { run += loc[i]; g_cum[tid*8 + i] = run; }
}

// ---------------- bf16 2-way split of x ----------------
__global__ void split_x_kernel(const float* __restrict__ x) {
    int i4 = blockIdx.x * blockDim.x + threadIdx.x;
    float4 v = ((const float4*)x)[i4];
    float a[4] = {v.x, v.y, v.z, v.w};
    __nv_bfloat16 h0[4], h1[4];
#pragma unroll
    for (int e = 0; e < 4; e++) {
        h0[e] = __float2bfloat16(a[e]);
        h1[e] = __float2bfloat16(a[e] - __bfloat162float(h0[e]));
    }
    __nv_bfloat162* p0 = (__nv_bfloat162*)g_xs0;
    __nv_bfloat162* p1 = (__nv_bfloat162*)g_xs1;
    p0[i4*2]   = __nv_bfloat162(h0[0], h0[1]); p0[i4*2+1] = __nv_bfloat162(h0[2], h0[3]);
    p1[i4*2]   = __nv_bfloat162(h1[0], h1[1]); p1[i4*2+1] = __nv_bfloat162(h1[2], h1[3]);
}

// ---------------- gather-split of ao: head-chunked -> [T][D] bf16 x2 ----------------
__global__ void split_ao_kernel() {
    int i4 = blockIdx.x * blockDim.x + threadIdx.x;  // T*D/4
    int t = i4 >> 8;
    int g = i4 & 255;
    int h = g >> 4, dh4 = (g & 15) * 4;
    float4 v = *(const float4*)(g_ao + (h*T + t)*DH + dh4);
    float a[4] = {v.x, v.y, v.z, v.w};
    __nv_bfloat16 h0[4], h1[4];
#pragma unroll
    for (int e = 0; e < 4; e++) {
        h0[e] = __float2bfloat16(a[e]);
        h1[e] = __float2bfloat16(a[e] - __bfloat162float(h0[e]));
    }
    int o2 = (t*D + h*64 + dh4) >> 1;
    __nv_bfloat162* p0 = (__nv_bfloat162*)g_as0;
    __nv_bfloat162* p1 = (__nv_bfloat162*)g_as1;
    p0[o2]   = __nv_bfloat162(h0[0], h0[1]); p0[o2+1] = __nv_bfloat162(h0[2], h0[3]);
    p1[o2]   = __nv_bfloat162(h1[0], h1[1]); p1[o2+1] = __nv_bfloat162(h1[2], h1[3]);
}

// ---------------- transpose + split of w_qkv: [K=1024][N3] -> ws[n][k] ----------------
__global__ void split_wt_kernel(const float* __restrict__ w) {
    __shared__ float t[32][33];
    int n0 = blockIdx.x * 32, k0 = blockIdx.y * 32;
    int tx = threadIdx.x & 31, ty = threadIdx.x >> 5;
#pragma unroll
    for (int r = 0; r < 4; r++)
        t[ty + 8*r][tx] = w[(k0 + ty + 8*r)*N3 + n0 + tx];
    __syncthreads();
#pragma unroll
    for (int r = 0; r < 4; r++) {
        int nn = ty + 8*r, kk = tx;
        float a = t[kk][nn];
        __nv_bfloat16 b0 = __float2bfloat16(a);
        __nv_bfloat16 b1 = __float2bfloat16(a - __bfloat162float(b0));
        int o = (n0 + nn)*D + k0 + kk;
        g_ws0[o] = b0; g_ws1[o] = b1;
    }
}

// ---------------- transpose + split of w_out: [K=1024][N=1024] -> wo[n][k] ----------------
__global__ void split_wo_kernel(const float* __restrict__ w) {
    __shared__ float t[32][33];
    int n0 = blockIdx.x * 32, k0 = blockIdx.y * 32;
    int tx = threadIdx.x & 31, ty = threadIdx.x >> 5;
#pragma unroll
    for (int r = 0; r < 4; r++)
        t[ty + 8*r][tx] = w[(k0 + ty + 8*r)*D + n0 + tx];
    __syncthreads();
#pragma unroll
    for (int r = 0; r < 4; r++) {
        int nn = ty + 8*r, kk = tx;
        float a = t[kk][nn];
        __nv_bfloat16 b0 = __float2bfloat16(a);
        __nv_bfloat16 b1 = __float2bfloat16(a - __bfloat162float(b0));
        int o = (n0 + nn)*D + k0 + kk;
        g_wo0[o] = b0; g_wo1[o] = b1;
    }
}

// ---------------- bf16 mma GEMM core (double-buffered cp.async) ----------------
// Block 128(M) x 128(N), 8 warps (warp 32x64), K chunks of 32, smem pitch 40 bf16.
#define SP 40
#define BUF_ELEMS (4*128*SP)            // 4 arrays per buffer
#define MMA_SMEM  (2*BUF_ELEMS*2)       // bytes

// stage one K-chunk into buffer: 4 arrays (A0,A1,B0,B1), 128 rows x 32 bf16 each
#define STAGE(buf, A0g, A1g, B0g, B1g, arow_base, brow_base, kt) do {               \
    __nv_bfloat16* _b = dsm + (buf)*BUF_ELEMS;                                       \
    _Pragma("unroll")                                                                \
    for (int r = 0; r < 2; r++) {                                                    \
        int idx = tid + r*256;                                                       \
        int row = idx >> 2, seg = idx & 3;                                           \
        int ga = ((arow_base) + row)*D + (kt)*32 + seg*8;                            \
        int gb = ((brow_base) + row)*D + (kt)*32 + seg*8;                            \
        int dsto = row*SP + seg*8;                                                   \
        cpa16(_b + dsto,              A0g + ga);                                     \
        cpa16(_b + 128*SP + dsto,     A1g + ga);                                     \
        cpa16(_b + 2*128*SP + dsto,   B0g + gb);                                     \
        cpa16(_b + 3*128*SP + dsto,   B1g + gb);                                     \
    }                                                                                \
    cpa_commit();                                                                    \
} while (0)

#define MMA_COMPUTE(buf) do {                                                        \
    __nv_bfloat16* As0 = dsm + (buf)*BUF_ELEMS;                                      \
    __nv_bfloat16* As1 = As0 + 128*SP;                                               \
    __nv_bfloat16* Bs0 = As0 + 2*128*SP;                                             \
    __nv_bfloat16* Bs1 = As0 + 3*128*SP;                                             \
    _Pragma("unroll")                                                                \
    for (int ks = 0; ks < 2; ks++) {                                                 \
        unsigned a0f[2][4], a1f[2][4], b0f[4][4], b1f[4][4];                         \
        _Pragma("unroll")                                                            \
        for (int mt = 0; mt < 2; mt++) {                                             \
            int off = (wm + mt*16 + a_r)*SP + ks*16 + a_c;                           \
            ldsm4(a0f[mt], As0 + off);                                               \
            ldsm4(a1f[mt], As1 + off);                                               \
        }                                                                            \
        _Pragma("unroll")                                                            \
        for (int nb = 0; nb < 4; nb++) {                                             \
            int off = (wn + nb*16 + b_r)*SP + ks*16 + b_c;                           \
            ldsm4(b0f[nb], Bs0 + off);                                               \
            ldsm4(b1f[nb], Bs1 + off);                                               \
        }                                                                            \
        _Pragma("unroll")                                                            \
        for (int mt = 0; mt < 2; mt++)                                               \
            _Pragma("unroll")                                                        \
            for (int nb = 0; nb < 4; nb++) {                                         \
                float* cLo = acc[mt][nb*2+0];                                        \
                float* cHi = acc[mt][nb*2+1];                                        \
                mma_bf16(cLo, a0f[mt], b0f[nb][0], b0f[nb][1]);                      \
                mma_bf16(cLo, a0f[mt], b1f[nb][0], b1f[nb][1]);                      \
                mma_bf16(cLo, a1f[mt], b0f[nb][0], b0f[nb][1]);                      \
                mma_bf16(cHi, a0f[mt], b0f[nb][2], b0f[nb][3]);                      \
                mma_bf16(cHi, a0f[mt], b1f[nb][2], b1f[nb][3]);                      \
                mma_bf16(cHi, a1f[mt], b0f[nb][2], b0f[nb][3]);                      \
            }                                                                        \
    }                                                                                \
} while (0)

#define MMA_PROLOG                                                                   \
    extern __shared__ __nv_bfloat16 dsm[];                                           \
    int tid = threadIdx.x;                                                           \
    int lane = tid & 31, warp = tid >> 5;                                            \
    int wm = (warp & 3) * 32, wn = (warp >> 2) * 64;                                 \
    float acc[2][8][4] = {};                                                         \
    int a_r = (lane & 7) + ((lane >> 3) & 1) * 8;                                    \
    int a_c = (lane >> 4) * 8;                                                       \
    int b_r = (lane & 7) + (lane >> 4) * 8;                                          \
    int b_c = ((lane >> 3) & 1) * 8;

#define MMA_MAINLOOP(A0g, A1g, B0g, B1g, arb, brb)                                   \
    STAGE(0, A0g, A1g, B0g, B1g, arb, brb, 0);                                       \
    for (int kt = 0; kt < 32; kt++) {                                                \
        int cur = kt & 1;                                                            \
        if (kt + 1 < 32) STAGE(cur ^ 1, A0g, A1g, B0g, B1g, arb, brb, kt + 1);       \
        if (kt + 1 < 32) cpa_wait1(); else cpa_wait0();                              \
        __syncthreads();                                                             \
        MMA_COMPUTE(cur);                                                            \
        __syncthreads();                                                             \
    }

// qkv: x(2048x1024) @ w_qkv^T-split + b, scatter to g_q/g_k/g_v (H,T,DH)
__global__ void __launch_bounds__(256, 1) qkv_mma_kernel(const float* __restrict__ bias) {
    MMA_PROLOG
    int bn = blockIdx.x, bm = blockIdx.y;
    MMA_MAINLOOP(g_xs0, g_xs1, g_ws0, g_ws1, bm*128, bn*128)

#pragma unroll
    for (int mt = 0; mt < 2; mt++) {
        int m0 = bm*128 + wm + mt*16 + (lane >> 2);
#pragma unroll
        for (int nb = 0; nb < 4; nb++)
#pragma unroll
            for (int half = 0; half < 2; half++) {
                int n0 = bn*128 + wn + nb*16 + half*8 + 2*(lane & 3);
                const float* C = acc[mt][nb*2+half];
#pragma unroll
                for (int e = 0; e < 4; e++) {
                    int m = m0 + (e >> 1) * 8;
                    int n = n0 + (e & 1);
                    float val = C[e] + __ldg(bias + n);
                    int qkv = n >> 10;
                    int h   = (n >> 6) & 15;
                    int dh  = n & 63;
                    float* dst = (qkv == 0) ? g_q : ((qkv == 1) ? g_k : g_v);
                    dst[(h*T + m)*DH + dh] = val;
                }
            }
    }
}

// out projection: ao-split(T x D) @ w_out^T-split + b_out -> xout
__global__ void __launch_bounds__(256, 1) out_mma_kernel(const float* __restrict__ bias,
                                                         float* __restrict__ xout) {
    MMA_PROLOG
    int bn = blockIdx.x, bm = blockIdx.y;
    MMA_MAINLOOP(g_as0, g_as1, g_wo0, g_wo1, bm*128, bn*128)

#pragma unroll
    for (int mt = 0; mt < 2; mt++) {
        int m0 = bm*128 + wm + mt*16 + (lane >> 2);
#pragma unroll
        for (int nb = 0; nb < 4; nb++)
#pragma unroll
            for (int half = 0; half < 2; half++) {
                int n0 = bn*128 + wn + nb*16 + half*8 + 2*(lane & 3);
                const float* C = acc[mt][nb*2+half];
#pragma unroll
                for (int e = 0; e < 4; e++) {
                    int m = m0 + (e >> 1) * 8;
                    int n = n0 + (e & 1);
                    xout[m*D + n] = C[e] + __ldg(bias + n);
                }
            }
    }
}

// ---------------- R[c]: per-chunk tail kv outer product ----------------
__global__ void chunk_kv_kernel() {
    __shared__ float kt[64][68];
    __shared__ float vt[64][64];
    int c = blockIdx.x;
    int h = blockIdx.y;
    int tid = threadIdx.x;
    int d = tid >> 2;
    int eg = (tid & 3) * 16;
    int t0 = c*64;
    int ctail = g_cum[t0 + 63];
    float acc[16] = {};
#pragma unroll
    for (int r = 0; r < 4; r++) {
        int idx = tid + r*256;
        int tt = idx >> 4, c4 = (idx & 15) * 4;
        int t = t0 + tt;
        float m = (g_cum[t] == ctail) ? 1.0f : 0.0f;
        float4 a = *(const float4*)(g_k + (h*T + t)*DH + c4);
        kt[tt][c4+0] = a.x*m; kt[tt][c4+1] = a.y*m;
        kt[tt][c4+2] = a.z*m; kt[tt][c4+3] = a.w*m;
        *(float4*)&vt[tt][c4] = *(const float4*)(g_v + (h*T + t)*DH + c4);
    }
    __syncthreads();
    for (int tt = 0; tt < 64; tt++) {
        float kv = kt[tt][d];
#pragma unroll
        for (int e4 = 0; e4 < 4; e4++) {
            float4 v4 = *(const float4*)&vt[tt][eg + e4*4];
            acc[e4*4+0] += kv * v4.x;
            acc[e4*4+1] += kv * v4.y;
            acc[e4*4+2] += kv * v4.z;
            acc[e4*4+3] += kv * v4.w;
        }
    }
    float* dst = &g_ns[c][h*4096 + d*64 + eg];
#pragma unroll
    for (int e = 0; e < 16; e++) dst[e] = acc[e];
}

// ---------------- segmented scan over chunks ----------------
__global__ void state_scan_kernel(const float* __restrict__ state,
                                  float* __restrict__ out_state) {
    int h = blockIdx.x, cg = blockIdx.y;
    int base = h*4096 + cg*1024 + threadIdx.x*4;
    float4 st = *(const float4*)(state + base);
    float4 S = make_float4(0.f, 0.f, 0.f, 0.f);
    int Eprev = 0;
    for (int c = 0; c < 32; c++) {
        float4 w = S;
        if (Eprev == 0) { w.x += st.x; w.y += st.y; w.z += st.z; w.w += st.w; }
        *(float4*)&g_Se[c][base] = w;
        int Ec = g_cum[c*64 + 63];
        float4 R = *(const float4*)&g_ns[c][base];
        if (Ec != Eprev) { S = R; }
        else { S.x += R.x; S.y += R.y; S.z += R.z; S.w += R.w; }
        Eprev = Ec;
    }
    float4 w = S;
    if (Eprev == 0) { w.x += st.x; w.y += st.y; w.z += st.z; w.w += st.w; }
    *(float4*)(out_state + base) = w;
}

// ---------------- chunked attention ----------------
__global__ void chunk_attn_kernel() {
    extern __shared__ float sm[];
    float* qs = sm;             // [64][68]  q transposed [d][t]
    float* ks = qs + 64*68;     // [64][68]  k transposed [d][s]; reused for Se [d][e]
    float* vs = ks + 64*68;     // [64][64]  [s][e]
    float* Ss = vs + 64*64;     // [64][68]  masked scores transposed [s][t]
    int*   cq = (int*)(Ss + 64*68);   // [64]

    int c = blockIdx.x, h = blockIdx.y;
    int t0 = c*64;
    int tid = threadIdx.x;
    int tx = tid & 15, ty = tid >> 4;

    const float* qg = g_q + (h*T + t0)*DH;
    const float* kg = g_k + (h*T + t0)*DH;
    const float* vg = g_v + (h*T + t0)*DH;
#pragma unroll
    for (int r = 0; r < 4; r++) {
        int idx = tid + r*256;
        int row = idx >> 4, c4 = (idx & 15) * 4;
        float4 a = *(const float4*)(qg + row*DH + c4);
        qs[(c4+0)*68 + row] = a.x; qs[(c4+1)*68 + row] = a.y;
        qs[(c4+2)*68 + row] = a.z; qs[(c4+3)*68 + row] = a.w;
        float4 bk = *(const float4*)(kg + row*DH + c4);
        ks[(c4+0)*68 + row] = bk.x; ks[(c4+1)*68 + row] = bk.y;
        ks[(c4+2)*68 + row] = bk.z; ks[(c4+3)*68 + row] = bk.w;
        *(float4*)&vs[row*64 + c4] = *(const float4*)(vg + row*DH + c4);
    }
    if (tid < 64) cq[tid] = g_cum[t0 + tid];
    __syncthreads();

    int prevE = (c == 0) ? 0 : g_cum[t0 - 1];

    float sacc[4][4] = {};
#pragma unroll 8
    for (int d = 0; d < 64; d++) {
        float4 av = *(const float4*)&qs[d*68 + ty*4];
        float4 bv = *(const float4*)&ks[d*68 + tx*4];
        float aa[4] = {av.x, av.y, av.z, av.w};
        float bb[4] = {bv.x, bv.y, bv.z, bv.w};
#pragma unroll
        for (int i = 0; i < 4; i++)
#pragma unroll
            for (int j = 0; j < 4; j++) sacc[i][j] += aa[i] * bb[j];
    }
#pragma unroll
    for (int j = 0; j < 4; j++) {
        int s_l = tx*4 + j;
        int cs  = cq[s_l];
        float tmp[4];
#pragma unroll
        for (int i = 0; i < 4; i++) {
            int t_l = ty*4 + i;
            bool m = (s_l <= t_l) && (cs == cq[t_l]);
            tmp[i] = m ? sacc[i][j] : 0.0f;
        }
        *(float4*)&Ss[s_l*68 + ty*4] = make_float4(tmp[0], tmp[1], tmp[2], tmp[3]);
    }
    __syncthreads();

    const float* seg = &g_Se[c][h*4096];
#pragma unroll
    for (int r = 0; r < 4; r++) {
        int idx = tid + r*256;
        int dd = idx >> 4, e4 = (idx & 15) * 4;
        *(float4*)&ks[dd*68 + e4] = *(const float4*)(seg + dd*64 + e4);
    }

    float acc[4][4] = {};
#pragma unroll 8
    for (int s = 0; s < 64; s++) {
        float4 av = *(const float4*)&Ss[s*68 + ty*4];
        float4 bv = *(const float4*)&vs[s*64 + tx*4];
        float aa[4] = {av.x, av.y, av.z, av.w};
        float bb[4] = {bv.x, bv.y, bv.z, bv.w};
#pragma unroll
        for (int i = 0; i < 4; i++)
#pragma unroll
            for (int j = 0; j < 4; j++) acc[i][j] += aa[i] * bb[j];
    }
    __syncthreads();

    float sacc2[4][4] = {};
#pragma unroll 8
    for (int d = 0; d < 64; d++) {
        float4 av = *(const float4*)&qs[d*68 + ty*4];
        float4 bv = *(const float4*)&ks[d*68 + tx*4];
        float aa[4] = {av.x, av.y, av.z, av.w};
        float bb[4] = {bv.x, bv.y, bv.z, bv.w};
#pragma unroll
        for (int i = 0; i < 4; i++)
#pragma unroll
            for (int j = 0; j < 4; j++) sacc2[i][j] += aa[i] * bb[j];
    }
#pragma unroll
    for (int i = 0; i < 4; i++) {
        if (cq[ty*4 + i] == prevE) {
#pragma unroll
            for (int j = 0; j < 4; j++) acc[i][j] += sacc2[i][j];
        }
    }

    float* og = g_ao + (h*T + t0)*DH;
#pragma unroll
    for (int i = 0; i < 4; i++) {
        *(float4*)&og[(ty*4+i)*DH + tx*4] = make_float4(acc[i][0], acc[i][1], acc[i][2], acc[i][3]);
    }
}

// ---------------- launch ----------------
static const int CA_SMEM = (64*68 + 64*68 + 64*64 + 64*68 + 64) * 4;

extern "C" void kernel_launch(void* const* d_in, const int* in_sizes, int n_in,
                              void* d_out, int out_size) {
    const float* state  = (const float*)d_in[0];
    const float* x      = (const float*)d_in[1];
    const unsigned char* done = (const unsigned char*)d_in[2];
    const float* w_qkv  = (const float*)d_in[3];
    const float* b_qkv  = (const float*)d_in[4];
    const float* w_out  = (const float*)d_in[5];
    const float* b_out  = (const float*)d_in[6];

    float* out_state = (float*)d_out;            // H*DH*DH = 65536 elems
    float* out_x     = out_state + H*DH*DH;      // T*D elems

    cudaFuncSetAttribute(chunk_attn_kernel, cudaFuncAttributeMaxDynamicSharedMemorySize, CA_SMEM);
    cudaFuncSetAttribute(qkv_mma_kernel, cudaFuncAttributeMaxDynamicSharedMemorySize, MMA_SMEM);
    cudaFuncSetAttribute(out_mma_kernel, cudaFuncAttributeMaxDynamicSharedMemorySize, MMA_SMEM);

    cumsum_kernel<<<1, 256>>>(done);
    split_x_kernel<<<2048, 256>>>(x);
    split_wt_kernel<<<dim3(N3/32, D/32), 256>>>(w_qkv);
    split_wo_kernel<<<dim3(D/32, D/32), 256>>>(w_out);
    qkv_mma_kernel<<<dim3(N3/128, T/128), 256, MMA_SMEM>>>(b_qkv);
    chunk_kv_kernel<<<dim3(32, H), 256>>>();
    state_scan_kernel<<<dim3(H, 4), 256>>>(state, out_state);
    chunk_attn_kernel<<<dim3(32, H), 256, CA_SMEM>>>();
    split_ao_kernel<<<2048, 256>>>();
    out_mma_kernel<<<dim3(D/128, T/128), 256, MMA_SMEM>>>(b_out, out_x);
}